// round 1
// baseline (speedup 1.0000x reference)
#include <cuda_runtime.h>

#define FULLM 0xffffffffu

static constexpr int Bc = 8, Nc = 8192, Dc = 32, Sc = 2048, Kc = 32;
static constexpr int Rc = Bc * Sc * Kc;  // 524288 rows

// ---------------- scratch (device globals: no allocations allowed) ----------
__device__ float4 g_xyzw[Bc * Nc];                     // x,y,z,|x|^2
__device__ int    g_knn[Rc];                           // neighbor indices
__device__ float  g_feat1[(long long)Rc * 64];         // pre-BN layer1, [64][R]
__device__ float  g_feat2[(long long)Rc * 64];         // pre-BN layer2, [64][R]
__device__ float  g_feat3[(long long)Rc * 128];        // pre-BN layer3, [128][R]
__device__ float  g_stats[256];                        // sum[0..127], sumsq[128..255]
__device__ float  g_ab[256];                           // a[0..C), c[C..2C)

// ---------------- kernel 0: pack xyz + squared norm --------------------------
__global__ void prep_kernel(const float* __restrict__ xyz) {
    int i = blockIdx.x * blockDim.x + threadIdx.x;
    if (i < Bc * Nc) {
        float x = xyz[3 * i + 0], y = xyz[3 * i + 1], z = xyz[3 * i + 2];
        float w = __fadd_rn(__fadd_rn(__fmul_rn(x, x), __fmul_rn(y, y)), __fmul_rn(z, z));
        g_xyzw[i] = make_float4(x, y, z, w);
    }
}

// ---------------- kernel 1: farthest point sampling ---------------------------
// One block per batch. Points and running min-dist live in registers.
// Distance arithmetic deliberately uses non-contracted fp32 mul/add to track the
// reference's sum((xyz - p)**2) semantics; argmax tie-breaks to smallest index.
__global__ __launch_bounds__(1024) void fps_kernel(const float* __restrict__ xyz,
                                                   float* __restrict__ out_xyz) {
    const int b = blockIdx.x;
    const float* X = xyz + (size_t)b * Nc * 3;
    float* O = out_xyz + (size_t)b * Sc * 3;
    const int t = threadIdx.x;

    float px_[8], py_[8], pz_[8], dist_[8];
#pragma unroll
    for (int j = 0; j < 8; j++) {
        int i = t + j * 1024;
        px_[j] = X[3 * i + 0];
        py_[j] = X[3 * i + 1];
        pz_[j] = X[3 * i + 2];
        dist_[j] = 1e10f;
    }

    __shared__ float s_v[32];
    __shared__ int s_i[32];
    __shared__ float s_px, s_py, s_pz;
    __shared__ int s_sel;

    if (t == 0) {
        s_px = X[0]; s_py = X[1]; s_pz = X[2];
        O[0] = X[0]; O[1] = X[1]; O[2] = X[2];
    }
    __syncthreads();

    for (int it = 1; it < Sc; ++it) {
        float qx = s_px, qy = s_py, qz = s_pz;
        float best = -1.0f;
        int bi = 0x7fffffff;
#pragma unroll
        for (int j = 0; j < 8; j++) {
            float dx = px_[j] - qx, dy = py_[j] - qy, dz = pz_[j] - qz;
            float d = __fadd_rn(__fadd_rn(__fmul_rn(dx, dx), __fmul_rn(dy, dy)),
                                __fmul_rn(dz, dz));
            float nd = fminf(dist_[j], d);
            dist_[j] = nd;
            if (nd > best) { best = nd; bi = j * 1024 + t; }
        }
#pragma unroll
        for (int o = 16; o; o >>= 1) {
            float v2 = __shfl_xor_sync(FULLM, best, o);
            int i2 = __shfl_xor_sync(FULLM, bi, o);
            if (v2 > best || (v2 == best && i2 < bi)) { best = v2; bi = i2; }
        }
        if ((t & 31) == 0) { s_v[t >> 5] = best; s_i[t >> 5] = bi; }
        __syncthreads();
        if (t < 32) {
            best = s_v[t]; bi = s_i[t];
#pragma unroll
            for (int o = 16; o; o >>= 1) {
                float v2 = __shfl_xor_sync(FULLM, best, o);
                int i2 = __shfl_xor_sync(FULLM, bi, o);
                if (v2 > best || (v2 == best && i2 < bi)) { best = v2; bi = i2; }
            }
            if (t == 0) s_sel = bi;
        }
        __syncthreads();
        int sel = s_sel;
        if ((sel & 1023) == t) {
            int j = sel >> 10;
            s_px = px_[j]; s_py = py_[j]; s_pz = pz_[j];
            O[3 * it + 0] = px_[j];
            O[3 * it + 1] = py_[j];
            O[3 * it + 2] = pz_[j];
        }
        __syncthreads();
    }
}

// ---------------- kernel 2: KNN (top-32 smallest) ----------------------------
// One warp per centroid, 8 warps/block; batch points staged in 128KB smem.
// Distance uses the reference's |c|^2 - 2 c.x + |x|^2 expansion.
__global__ __launch_bounds__(256) void knn_kernel(const float* __restrict__ newxyz) {
    extern __shared__ float4 s_pts[];
    int b = blockIdx.x >> 8;        // 256 groups per batch
    int grp = blockIdx.x & 255;
    const float4* P = g_xyzw + (size_t)b * Nc;
    for (int i = threadIdx.x; i < Nc; i += 256) s_pts[i] = P[i];
    __syncthreads();

    int warp = threadIdx.x >> 5, lane = threadIdx.x & 31;
    int s = grp * 8 + warp;
    int bs = b * Sc + s;
    float cx = newxyz[3 * bs], cy = newxyz[3 * bs + 1], cz = newxyz[3 * bs + 2];
    float cn = __fadd_rn(__fadd_rn(__fmul_rn(cx, cx), __fmul_rn(cy, cy)), __fmul_rn(cz, cz));

    float4 p = s_pts[lane];
    float dot = __fadd_rn(__fadd_rn(__fmul_rn(cx, p.x), __fmul_rn(cy, p.y)), __fmul_rn(cz, p.z));
    float kd = __fadd_rn(__fsub_rn(cn, __fmul_rn(2.0f, dot)), p.w);
    int ki = lane;

    float cm = kd;
#pragma unroll
    for (int o = 16; o; o >>= 1) cm = fmaxf(cm, __shfl_xor_sync(FULLM, cm, o));

    for (int base = 32; base < Nc; base += 32) {
        p = s_pts[base + lane];
        dot = __fadd_rn(__fadd_rn(__fmul_rn(cx, p.x), __fmul_rn(cy, p.y)), __fmul_rn(cz, p.z));
        float d = __fadd_rn(__fsub_rn(cn, __fmul_rn(2.0f, dot)), p.w);
        unsigned m = __ballot_sync(FULLM, d < cm);
        while (m) {
            int src = __ffs(m) - 1;
            m &= m - 1;
            float dn = __shfl_sync(FULLM, d, src);
            if (dn < cm) {
                unsigned mm = __ballot_sync(FULLM, kd == cm);
                int vic = __ffs(mm) - 1;
                if (lane == vic) { kd = dn; ki = base + src; }
                float v = kd;
#pragma unroll
                for (int o = 16; o; o >>= 1) v = fmaxf(v, __shfl_xor_sync(FULLM, v, o));
                cm = v;
            }
        }
    }
    g_knn[bs * 32 + lane] = ki;
}

// ---------------- kernels 3/5/7: 1x1 conv layers ------------------------------
// Thread computes 32 output channels for one row. Weights transposed into smem
// ([c][o] so warp reads are broadcast float4). Features channel-major [C][R]
// so global loads/stores are fully coalesced. LAYER==1 gathers inputs (knn).
template <int LAYER>
__global__ __launch_bounds__(256) void mlp_kernel(const float* __restrict__ W,
                                                  const float* __restrict__ Bias,
                                                  const float* __restrict__ pts,
                                                  const float* __restrict__ newxyz) {
    constexpr int CIN = (LAYER == 1) ? 35 : 64;
    constexpr int COUT = (LAYER == 3) ? 128 : 64;
    constexpr int TPR = COUT / 32;
    constexpr int RPB = 256 / TPR;

    const float* fin = (LAYER == 2) ? g_feat1 : g_feat2;
    float* fout = (LAYER == 1) ? g_feat1 : (LAYER == 2) ? g_feat2 : g_feat3;

    __shared__ float s_w[CIN * COUT];
    __shared__ float s_b[COUT];
    __shared__ float s_a[64], s_c[64];

    for (int idx = threadIdx.x; idx < CIN * COUT; idx += 256) {
        int o = idx / CIN, c = idx % CIN;
        s_w[c * COUT + o] = W[idx];
    }
    if (threadIdx.x < COUT) s_b[threadIdx.x] = Bias[threadIdx.x];
    if (LAYER > 1 && threadIdx.x < CIN) {
        s_a[threadIdx.x] = g_ab[threadIdx.x];
        s_c[threadIdx.x] = g_ab[CIN + threadIdx.x];
    }
    __syncthreads();

    int r = blockIdx.x * RPB + (threadIdx.x & (RPB - 1));
    int ot = (threadIdx.x / RPB) * 32;

    float in[CIN];
    if (LAYER == 1) {
        int b = r >> 16;
        int rem = r & 65535;
        int s = rem >> 5;
        int n = g_knn[r];
        float4 p = g_xyzw[b * Nc + n];
        int bs = b * Sc + s;
        in[0] = p.x - newxyz[3 * bs + 0];
        in[1] = p.y - newxyz[3 * bs + 1];
        in[2] = p.z - newxyz[3 * bs + 2];
        const float4* pp = (const float4*)(pts + (size_t)(b * Nc + n) * Dc);
#pragma unroll
        for (int q = 0; q < 8; q++) {
            float4 v = pp[q];
            in[3 + 4 * q] = v.x; in[4 + 4 * q] = v.y;
            in[5 + 4 * q] = v.z; in[6 + 4 * q] = v.w;
        }
    } else {
#pragma unroll
        for (int c = 0; c < CIN; c++) {
            float xv = fin[(size_t)c * Rc + r];
            in[c] = fmaxf(fmaf(s_a[c], xv, s_c[c]), 0.0f);
        }
    }

    float acc[32];
#pragma unroll
    for (int oo = 0; oo < 32; oo++) acc[oo] = s_b[ot + oo];
#pragma unroll
    for (int c = 0; c < CIN; c++) {
        float v = in[c];
        const float4* wr = (const float4*)(s_w + c * COUT + ot);
#pragma unroll
        for (int o4 = 0; o4 < 8; o4++) {
            float4 w = wr[o4];
            acc[4 * o4 + 0] = fmaf(v, w.x, acc[4 * o4 + 0]);
            acc[4 * o4 + 1] = fmaf(v, w.y, acc[4 * o4 + 1]);
            acc[4 * o4 + 2] = fmaf(v, w.z, acc[4 * o4 + 2]);
            acc[4 * o4 + 3] = fmaf(v, w.w, acc[4 * o4 + 3]);
        }
    }
#pragma unroll
    for (int oo = 0; oo < 32; oo++) fout[(size_t)(ot + oo) * Rc + r] = acc[oo];
}

// ---------------- BN statistics -----------------------------------------------
__global__ void zero_stats() { g_stats[threadIdx.x] = 0.0f; }

__global__ __launch_bounds__(256) void stats_kernel(int which) {
    const float* f = (which == 0) ? g_feat1 : (which == 1) ? g_feat2 : g_feat3;
    int o = blockIdx.x >> 5;
    int ch = blockIdx.x & 31;
    const float4* p = (const float4*)(f + (size_t)o * Rc) + (size_t)ch * (Rc / 32 / 4);
    float s = 0.0f, sq = 0.0f;
    for (int i = threadIdx.x; i < Rc / 32 / 4; i += 256) {
        float4 v = p[i];
        s += v.x + v.y + v.z + v.w;
        sq = fmaf(v.x, v.x, sq);
        sq = fmaf(v.y, v.y, sq);
        sq = fmaf(v.z, v.z, sq);
        sq = fmaf(v.w, v.w, sq);
    }
#pragma unroll
    for (int off = 16; off; off >>= 1) {
        s += __shfl_xor_sync(FULLM, s, off);
        sq += __shfl_xor_sync(FULLM, sq, off);
    }
    __shared__ float sh[16];
    int warp = threadIdx.x >> 5, lane = threadIdx.x & 31;
    if (lane == 0) { sh[warp] = s; sh[8 + warp] = sq; }
    __syncthreads();
    if (threadIdx.x == 0) {
        float ts = 0.0f, tq = 0.0f;
        for (int w = 0; w < 8; w++) { ts += sh[w]; tq += sh[8 + w]; }
        atomicAdd(&g_stats[o], ts);
        atomicAdd(&g_stats[128 + o], tq);
    }
}

__global__ void finalize_kernel(const float* __restrict__ g,
                                const float* __restrict__ be, int C) {
    int o = threadIdx.x;
    if (o < C) {
        const float inv = 1.0f / (float)Rc;
        float mu = g_stats[o] * inv;
        float var = g_stats[128 + o] * inv - mu * mu;
        float a = g[o] * rsqrtf(var + 1e-5f);
        g_ab[o] = a;
        g_ab[C + o] = fmaf(-mu, a, be[o]);
    }
}

// ---------------- kernel 8: BN+ReLU+maxpool over K ----------------------------
__global__ __launch_bounds__(256) void maxpool_kernel(float* __restrict__ outp) {
    int idx = blockIdx.x * 256 + threadIdx.x;  // (b*S+s)*128 + o
    int o = idx & 127;
    int bs = idx >> 7;
    float a = g_ab[o], c = g_ab[128 + o];
    const float4* p = (const float4*)(g_feat3 + (size_t)o * Rc + (size_t)bs * 32);
    float m = 0.0f;  // relu baked in: max(y_k, 0)
#pragma unroll
    for (int q = 0; q < 8; q++) {
        float4 v = p[q];
        m = fmaxf(m, fmaf(a, v.x, c));
        m = fmaxf(m, fmaf(a, v.y, c));
        m = fmaxf(m, fmaf(a, v.z, c));
        m = fmaxf(m, fmaf(a, v.w, c));
    }
    outp[idx] = m;
}

// ---------------- launch --------------------------------------------------------
extern "C" void kernel_launch(void* const* d_in, const int* in_sizes, int n_in,
                              void* d_out, int out_size) {
    const float* xyz = (const float*)d_in[0];
    const float* points = (const float*)d_in[1];
    const float* w1 = (const float*)d_in[2];
    const float* b1 = (const float*)d_in[3];
    const float* g1 = (const float*)d_in[4];
    const float* be1 = (const float*)d_in[5];
    const float* w2 = (const float*)d_in[6];
    const float* b2 = (const float*)d_in[7];
    const float* g2 = (const float*)d_in[8];
    const float* be2 = (const float*)d_in[9];
    const float* w3 = (const float*)d_in[10];
    const float* b3 = (const float*)d_in[11];
    const float* g3 = (const float*)d_in[12];
    const float* be3 = (const float*)d_in[13];

    float* out = (float*)d_out;
    float* out_xyz = out;                      // [B,S,3]
    float* out_pts = out + (size_t)Bc * Sc * 3;  // [B,S,128]

    prep_kernel<<<(Bc * Nc + 255) / 256, 256>>>(xyz);
    fps_kernel<<<Bc, 1024>>>(xyz, out_xyz);

    cudaFuncSetAttribute(knn_kernel, cudaFuncAttributeMaxDynamicSharedMemorySize,
                         Nc * (int)sizeof(float4));
    knn_kernel<<<Bc * (Sc / 8), 256, Nc * sizeof(float4)>>>(out_xyz);

    mlp_kernel<1><<<Rc / 128, 256>>>(w1, b1, points, out_xyz);
    zero_stats<<<1, 256>>>();
    stats_kernel<<<64 * 32, 256>>>(0);
    finalize_kernel<<<1, 128>>>(g1, be1, 64);

    mlp_kernel<2><<<Rc / 128, 256>>>(w2, b2, points, out_xyz);
    zero_stats<<<1, 256>>>();
    stats_kernel<<<64 * 32, 256>>>(1);
    finalize_kernel<<<1, 128>>>(g2, be2, 64);

    mlp_kernel<3><<<Rc / 64, 256>>>(w3, b3, points, out_xyz);
    zero_stats<<<1, 256>>>();
    stats_kernel<<<128 * 32, 256>>>(2);
    finalize_kernel<<<1, 128>>>(g3, be3, 128);

    maxpool_kernel<<<(Bc * Sc * 128) / 256, 256>>>(out_pts);
}

// round 2
// speedup vs baseline: 1.0890x; 1.0890x over previous
#include <cuda_runtime.h>

#define FULLM 0xffffffffu

static constexpr int Bc = 8, Nc = 8192, Dc = 32, Sc = 2048, Kc = 32;
static constexpr int Rc = Bc * Sc * Kc;  // 524288 rows

// ---------------- scratch (device globals: no allocations allowed) ----------
__device__ float4 g_xyzw[Bc * Nc];                     // x,y,z,|x|^2
__device__ int    g_knn[Rc];                           // neighbor indices
__device__ float  g_feat1[(long long)Rc * 64];         // pre-BN layer1, [64][R]
__device__ float  g_feat2[(long long)Rc * 64];         // pre-BN layer2, [64][R]
__device__ float  g_feat3[(long long)Rc * 128];        // pre-BN layer3, [128][R]
__device__ float  g_stats[256];                        // sum[0..127], sumsq[128..255]
__device__ float  g_ab[256];                           // a[0..C), c[C..2C)

// ---------------- kernel 0: pack xyz + squared norm --------------------------
__global__ void prep_kernel(const float* __restrict__ xyz) {
    int i = blockIdx.x * blockDim.x + threadIdx.x;
    if (i < Bc * Nc) {
        float x = xyz[3 * i + 0], y = xyz[3 * i + 1], z = xyz[3 * i + 2];
        float w = __fadd_rn(__fadd_rn(__fmul_rn(x, x), __fmul_rn(y, y)), __fmul_rn(z, z));
        g_xyzw[i] = make_float4(x, y, z, w);
    }
}

// ---------------- kernel 1: farthest point sampling ---------------------------
// One block per batch, 512 threads x 16 points. Packed f32x2 arithmetic (bit-
// exact per-lane IEEE RN, matching the reference's sum((xyz-p)**2) with
// subtraction expressed as add-of-negation). Single barrier per iteration:
// warp shfl argmax -> lane0 atomicMax on a 64-bit smem key -> sync -> decode.
// Tie-break: larger dist wins; equal dist -> smaller index (via ~idx in key).
__global__ __launch_bounds__(512) void fps_kernel(const float* __restrict__ xyz,
                                                  float* __restrict__ out_xyz) {
    const int b = blockIdx.x;
    const float* X = xyz + (size_t)b * Nc * 3;
    float* O = out_xyz + (size_t)b * Sc * 3;
    const int t = threadIdx.x;

    // 16 contiguous points per thread: indices 16t .. 16t+15, packed in pairs.
    unsigned long long xp[8], yp[8], zp[8];
    float dist[16];
#pragma unroll
    for (int j = 0; j < 8; j++) {
        int i0 = 16 * t + 2 * j;
        float x0 = X[3 * i0 + 0], y0 = X[3 * i0 + 1], z0 = X[3 * i0 + 2];
        float x1 = X[3 * i0 + 3], y1 = X[3 * i0 + 4], z1 = X[3 * i0 + 5];
        asm("mov.b64 %0, {%1,%2};" : "=l"(xp[j]) : "f"(x0), "f"(x1));
        asm("mov.b64 %0, {%1,%2};" : "=l"(yp[j]) : "f"(y0), "f"(y1));
        asm("mov.b64 %0, {%1,%2};" : "=l"(zp[j]) : "f"(z0), "f"(z1));
        dist[2 * j] = 1e10f;
        dist[2 * j + 1] = 1e10f;
    }

    __shared__ unsigned long long s_key[4];
    if (t < 4) s_key[t] = 0ull;

    float qx = X[0], qy = X[1], qz = X[2];
    if (t == 0) { O[0] = qx; O[1] = qy; O[2] = qz; }
    __syncthreads();

    for (int it = 1; it < Sc; ++it) {
        float nqx = -qx, nqy = -qy, nqz = -qz;
        unsigned long long nq_x, nq_y, nq_z;
        asm("mov.b64 %0, {%1,%1};" : "=l"(nq_x) : "f"(nqx));
        asm("mov.b64 %0, {%1,%1};" : "=l"(nq_y) : "f"(nqy));
        asm("mov.b64 %0, {%1,%1};" : "=l"(nq_z) : "f"(nqz));

        float best = -1.0f;
        int bi = 0x7fffffff;
#pragma unroll
        for (int j = 0; j < 8; j++) {
            unsigned long long dx, dy, dz, sx, sy, sz, s;
            asm("add.rn.f32x2 %0, %1, %2;" : "=l"(dx) : "l"(xp[j]), "l"(nq_x));
            asm("add.rn.f32x2 %0, %1, %2;" : "=l"(dy) : "l"(yp[j]), "l"(nq_y));
            asm("add.rn.f32x2 %0, %1, %2;" : "=l"(dz) : "l"(zp[j]), "l"(nq_z));
            asm("mul.rn.f32x2 %0, %1, %1;" : "=l"(sx) : "l"(dx));
            asm("mul.rn.f32x2 %0, %1, %1;" : "=l"(sy) : "l"(dy));
            asm("mul.rn.f32x2 %0, %1, %1;" : "=l"(sz) : "l"(dz));
            asm("add.rn.f32x2 %0, %1, %2;" : "=l"(s) : "l"(sx), "l"(sy));
            asm("add.rn.f32x2 %0, %1, %2;" : "=l"(s) : "l"(s), "l"(sz));
            float d0, d1;
            asm("mov.b64 {%0,%1}, %2;" : "=f"(d0), "=f"(d1) : "l"(s));
            float nd0 = fminf(dist[2 * j], d0);
            dist[2 * j] = nd0;
            if (nd0 > best) { best = nd0; bi = 16 * t + 2 * j; }
            float nd1 = fminf(dist[2 * j + 1], d1);
            dist[2 * j + 1] = nd1;
            if (nd1 > best) { best = nd1; bi = 16 * t + 2 * j + 1; }
        }
#pragma unroll
        for (int o = 16; o; o >>= 1) {
            float v2 = __shfl_xor_sync(FULLM, best, o);
            int i2 = __shfl_xor_sync(FULLM, bi, o);
            if (v2 > best || (v2 == best && i2 < bi)) { best = v2; bi = i2; }
        }
        if ((t & 31) == 0) {
            unsigned long long key =
                ((unsigned long long)__float_as_uint(best) << 32) |
                (unsigned long long)(0xffffffffu - (unsigned)bi);
            atomicMax(&s_key[it & 3], key);
        }
        if (t == 0) s_key[(it + 2) & 3] = 0ull;  // slot reuse separated by 2 barriers
        __syncthreads();
        unsigned long long key = s_key[it & 3];
        int sel = (int)(0xffffffffu - (unsigned)(key & 0xffffffffu));
        qx = __ldg(&X[3 * sel + 0]);
        qy = __ldg(&X[3 * sel + 1]);
        qz = __ldg(&X[3 * sel + 2]);
        if (t == 0) { O[3 * it + 0] = qx; O[3 * it + 1] = qy; O[3 * it + 2] = qz; }
    }
}

// ---------------- kernel 2: KNN (top-32 smallest) ----------------------------
__global__ __launch_bounds__(256) void knn_kernel(const float* __restrict__ newxyz) {
    extern __shared__ float4 s_pts[];
    int b = blockIdx.x >> 8;        // 256 groups per batch
    int grp = blockIdx.x & 255;
    const float4* P = g_xyzw + (size_t)b * Nc;
    for (int i = threadIdx.x; i < Nc; i += 256) s_pts[i] = P[i];
    __syncthreads();

    int warp = threadIdx.x >> 5, lane = threadIdx.x & 31;
    int s = grp * 8 + warp;
    int bs = b * Sc + s;
    float cx = newxyz[3 * bs], cy = newxyz[3 * bs + 1], cz = newxyz[3 * bs + 2];
    float cn = __fadd_rn(__fadd_rn(__fmul_rn(cx, cx), __fmul_rn(cy, cy)), __fmul_rn(cz, cz));

    float4 p = s_pts[lane];
    float dot = __fadd_rn(__fadd_rn(__fmul_rn(cx, p.x), __fmul_rn(cy, p.y)), __fmul_rn(cz, p.z));
    float kd = __fadd_rn(__fsub_rn(cn, __fmul_rn(2.0f, dot)), p.w);
    int ki = lane;

    float cm = kd;
#pragma unroll
    for (int o = 16; o; o >>= 1) cm = fmaxf(cm, __shfl_xor_sync(FULLM, cm, o));

    for (int base = 32; base < Nc; base += 32) {
        p = s_pts[base + lane];
        dot = __fadd_rn(__fadd_rn(__fmul_rn(cx, p.x), __fmul_rn(cy, p.y)), __fmul_rn(cz, p.z));
        float d = __fadd_rn(__fsub_rn(cn, __fmul_rn(2.0f, dot)), p.w);
        unsigned m = __ballot_sync(FULLM, d < cm);
        while (m) {
            int src = __ffs(m) - 1;
            m &= m - 1;
            float dn = __shfl_sync(FULLM, d, src);
            if (dn < cm) {
                unsigned mm = __ballot_sync(FULLM, kd == cm);
                int vic = __ffs(mm) - 1;
                if (lane == vic) { kd = dn; ki = base + src; }
                float v = kd;
#pragma unroll
                for (int o = 16; o; o >>= 1) v = fmaxf(v, __shfl_xor_sync(FULLM, v, o));
                cm = v;
            }
        }
    }
    g_knn[bs * 32 + lane] = ki;
}

// ---------------- kernels 3/5/7: 1x1 conv layers ------------------------------
template <int LAYER>
__global__ __launch_bounds__(256) void mlp_kernel(const float* __restrict__ W,
                                                  const float* __restrict__ Bias,
                                                  const float* __restrict__ pts,
                                                  const float* __restrict__ newxyz) {
    constexpr int CIN = (LAYER == 1) ? 35 : 64;
    constexpr int COUT = (LAYER == 3) ? 128 : 64;
    constexpr int TPR = COUT / 32;
    constexpr int RPB = 256 / TPR;

    const float* fin = (LAYER == 2) ? g_feat1 : g_feat2;
    float* fout = (LAYER == 1) ? g_feat1 : (LAYER == 2) ? g_feat2 : g_feat3;

    __shared__ float s_w[CIN * COUT];
    __shared__ float s_b[COUT];
    __shared__ float s_a[64], s_c[64];

    for (int idx = threadIdx.x; idx < CIN * COUT; idx += 256) {
        int o = idx / CIN, c = idx % CIN;
        s_w[c * COUT + o] = W[idx];
    }
    if (threadIdx.x < COUT) s_b[threadIdx.x] = Bias[threadIdx.x];
    if (LAYER > 1 && threadIdx.x < CIN) {
        s_a[threadIdx.x] = g_ab[threadIdx.x];
        s_c[threadIdx.x] = g_ab[CIN + threadIdx.x];
    }
    __syncthreads();

    int r = blockIdx.x * RPB + (threadIdx.x & (RPB - 1));
    int ot = (threadIdx.x / RPB) * 32;

    float in[CIN];
    if (LAYER == 1) {
        int b = r >> 16;
        int rem = r & 65535;
        int s = rem >> 5;
        int n = g_knn[r];
        float4 p = g_xyzw[b * Nc + n];
        int bs = b * Sc + s;
        in[0] = p.x - newxyz[3 * bs + 0];
        in[1] = p.y - newxyz[3 * bs + 1];
        in[2] = p.z - newxyz[3 * bs + 2];
        const float4* pp = (const float4*)(pts + (size_t)(b * Nc + n) * Dc);
#pragma unroll
        for (int q = 0; q < 8; q++) {
            float4 v = pp[q];
            in[3 + 4 * q] = v.x; in[4 + 4 * q] = v.y;
            in[5 + 4 * q] = v.z; in[6 + 4 * q] = v.w;
        }
    } else {
#pragma unroll
        for (int c = 0; c < CIN; c++) {
            float xv = fin[(size_t)c * Rc + r];
            in[c] = fmaxf(fmaf(s_a[c], xv, s_c[c]), 0.0f);
        }
    }

    float acc[32];
#pragma unroll
    for (int oo = 0; oo < 32; oo++) acc[oo] = s_b[ot + oo];
#pragma unroll
    for (int c = 0; c < CIN; c++) {
        float v = in[c];
        const float4* wr = (const float4*)(s_w + c * COUT + ot);
#pragma unroll
        for (int o4 = 0; o4 < 8; o4++) {
            float4 w = wr[o4];
            acc[4 * o4 + 0] = fmaf(v, w.x, acc[4 * o4 + 0]);
            acc[4 * o4 + 1] = fmaf(v, w.y, acc[4 * o4 + 1]);
            acc[4 * o4 + 2] = fmaf(v, w.z, acc[4 * o4 + 2]);
            acc[4 * o4 + 3] = fmaf(v, w.w, acc[4 * o4 + 3]);
        }
    }
#pragma unroll
    for (int oo = 0; oo < 32; oo++) fout[(size_t)(ot + oo) * Rc + r] = acc[oo];
}

// ---------------- BN statistics -----------------------------------------------
__global__ void zero_stats() { g_stats[threadIdx.x] = 0.0f; }

__global__ __launch_bounds__(256) void stats_kernel(int which) {
    const float* f = (which == 0) ? g_feat1 : (which == 1) ? g_feat2 : g_feat3;
    int o = blockIdx.x >> 5;
    int ch = blockIdx.x & 31;
    const float4* p = (const float4*)(f + (size_t)o * Rc) + (size_t)ch * (Rc / 32 / 4);
    float s = 0.0f, sq = 0.0f;
    for (int i = threadIdx.x; i < Rc / 32 / 4; i += 256) {
        float4 v = p[i];
        s += v.x + v.y + v.z + v.w;
        sq = fmaf(v.x, v.x, sq);
        sq = fmaf(v.y, v.y, sq);
        sq = fmaf(v.z, v.z, sq);
        sq = fmaf(v.w, v.w, sq);
    }
#pragma unroll
    for (int off = 16; off; off >>= 1) {
        s += __shfl_xor_sync(FULLM, s, off);
        sq += __shfl_xor_sync(FULLM, sq, off);
    }
    __shared__ float sh[16];
    int warp = threadIdx.x >> 5, lane = threadIdx.x & 31;
    if (lane == 0) { sh[warp] = s; sh[8 + warp] = sq; }
    __syncthreads();
    if (threadIdx.x == 0) {
        float ts = 0.0f, tq = 0.0f;
        for (int w = 0; w < 8; w++) { ts += sh[w]; tq += sh[8 + w]; }
        atomicAdd(&g_stats[o], ts);
        atomicAdd(&g_stats[128 + o], tq);
    }
}

__global__ void finalize_kernel(const float* __restrict__ g,
                                const float* __restrict__ be, int C) {
    int o = threadIdx.x;
    if (o < C) {
        const float inv = 1.0f / (float)Rc;
        float mu = g_stats[o] * inv;
        float var = g_stats[128 + o] * inv - mu * mu;
        float a = g[o] * rsqrtf(var + 1e-5f);
        g_ab[o] = a;
        g_ab[C + o] = fmaf(-mu, a, be[o]);
    }
}

// ---------------- kernel 8: BN+ReLU+maxpool over K ----------------------------
__global__ __launch_bounds__(256) void maxpool_kernel(float* __restrict__ outp) {
    int idx = blockIdx.x * 256 + threadIdx.x;  // (b*S+s)*128 + o
    int o = idx & 127;
    int bs = idx >> 7;
    float a = g_ab[o], c = g_ab[128 + o];
    const float4* p = (const float4*)(g_feat3 + (size_t)o * Rc + (size_t)bs * 32);
    float m = 0.0f;  // relu baked in
#pragma unroll
    for (int q = 0; q < 8; q++) {
        float4 v = p[q];
        m = fmaxf(m, fmaf(a, v.x, c));
        m = fmaxf(m, fmaf(a, v.y, c));
        m = fmaxf(m, fmaf(a, v.z, c));
        m = fmaxf(m, fmaf(a, v.w, c));
    }
    outp[idx] = m;
}

// ---------------- launch --------------------------------------------------------
extern "C" void kernel_launch(void* const* d_in, const int* in_sizes, int n_in,
                              void* d_out, int out_size) {
    const float* xyz = (const float*)d_in[0];
    const float* points = (const float*)d_in[1];
    const float* w1 = (const float*)d_in[2];
    const float* b1 = (const float*)d_in[3];
    const float* g1 = (const float*)d_in[4];
    const float* be1 = (const float*)d_in[5];
    const float* w2 = (const float*)d_in[6];
    const float* b2 = (const float*)d_in[7];
    const float* g2 = (const float*)d_in[8];
    const float* be2 = (const float*)d_in[9];
    const float* w3 = (const float*)d_in[10];
    const float* b3 = (const float*)d_in[11];
    const float* g3 = (const float*)d_in[12];
    const float* be3 = (const float*)d_in[13];

    float* out = (float*)d_out;
    float* out_xyz = out;                        // [B,S,3]
    float* out_pts = out + (size_t)Bc * Sc * 3;  // [B,S,128]

    prep_kernel<<<(Bc * Nc + 255) / 256, 256>>>(xyz);
    fps_kernel<<<Bc, 512>>>(xyz, out_xyz);

    cudaFuncSetAttribute(knn_kernel, cudaFuncAttributeMaxDynamicSharedMemorySize,
                         Nc * (int)sizeof(float4));
    knn_kernel<<<Bc * (Sc / 8), 256, Nc * sizeof(float4)>>>(out_xyz);

    mlp_kernel<1><<<Rc / 128, 256>>>(w1, b1, points, out_xyz);
    zero_stats<<<1, 256>>>();
    stats_kernel<<<64 * 32, 256>>>(0);
    finalize_kernel<<<1, 128>>>(g1, be1, 64);

    mlp_kernel<2><<<Rc / 128, 256>>>(w2, b2, points, out_xyz);
    zero_stats<<<1, 256>>>();
    stats_kernel<<<64 * 32, 256>>>(1);
    finalize_kernel<<<1, 128>>>(g2, be2, 64);

    mlp_kernel<3><<<Rc / 64, 256>>>(w3, b3, points, out_xyz);
    zero_stats<<<1, 256>>>();
    stats_kernel<<<128 * 32, 256>>>(2);
    finalize_kernel<<<1, 128>>>(g3, be3, 128);

    maxpool_kernel<<<(Bc * Sc * 128) / 256, 256>>>(out_pts);
}

// round 3
// speedup vs baseline: 1.2376x; 1.1364x over previous
#include <cuda_runtime.h>

#define FULLM 0xffffffffu

static constexpr int Bc = 8, Nc = 8192, Dc = 32, Sc = 2048, Kc = 32;
static constexpr int Rc = Bc * Sc * Kc;  // 524288 rows

// ---------------- scratch (device globals: no allocations allowed) ----------
__device__ float4 g_xyzw[Bc * Nc];                     // x,y,z,|x|^2
__device__ int    g_knn[Rc];                           // neighbor indices
__device__ float  g_feat1[(long long)Rc * 64];         // pre-BN layer1, [64][R]
__device__ float  g_feat2[(long long)Rc * 64];         // pre-BN layer2, [64][R]
__device__ float  g_feat3[(long long)Rc * 128];        // pre-BN layer3, [128][R]
__device__ float  g_stats[256];                        // sum[0..127], sumsq[128..255]
__device__ float  g_ab[256];                           // a[0..C), c[C..2C)

// ---------------- kernel 0: pack xyz + squared norm --------------------------
__global__ void prep_kernel(const float* __restrict__ xyz) {
    int i = blockIdx.x * blockDim.x + threadIdx.x;
    if (i < Bc * Nc) {
        float x = xyz[3 * i + 0], y = xyz[3 * i + 1], z = xyz[3 * i + 2];
        float w = __fadd_rn(__fadd_rn(__fmul_rn(x, x), __fmul_rn(y, y)), __fmul_rn(z, z));
        g_xyzw[i] = make_float4(x, y, z, w);
    }
}

// ---------------- kernel 1: farthest point sampling ---------------------------
// One block per batch, 512 threads x 16 points, packed f32x2 arithmetic
// (bit-exact per-lane IEEE RN vs the reference's sum((xyz-p)**2)).
// Per iteration: redux.sync argmax (dist bits are non-negative, so unsigned
// order == float order; lowest lane / ~idx keys preserve smallest-index
// tie-break) -> lane0 atomicMax 64-bit smem key -> one barrier -> winner point
// broadcast from SMEM (29cyc LDS instead of L2 round trip).
__global__ __launch_bounds__(512) void fps_kernel(const float* __restrict__ xyz,
                                                  float* __restrict__ out_xyz) {
    const int b = blockIdx.x;
    const float* X = xyz + (size_t)b * Nc * 3;
    float* O = out_xyz + (size_t)b * Sc * 3;
    const int t = threadIdx.x;

    __shared__ float s_x[Nc * 3];                 // 96KB point stash
    __shared__ unsigned long long s_key[4];

    for (int i = t; i < Nc * 3; i += 512) s_x[i] = X[i];
    if (t < 4) s_key[t] = 0ull;

    // 16 contiguous points per thread, packed in pairs.
    unsigned long long xp[8], yp[8], zp[8];
    float dist[16];
#pragma unroll
    for (int j = 0; j < 8; j++) {
        int i0 = 16 * t + 2 * j;
        float x0 = X[3 * i0 + 0], y0 = X[3 * i0 + 1], z0 = X[3 * i0 + 2];
        float x1 = X[3 * i0 + 3], y1 = X[3 * i0 + 4], z1 = X[3 * i0 + 5];
        asm("mov.b64 %0, {%1,%2};" : "=l"(xp[j]) : "f"(x0), "f"(x1));
        asm("mov.b64 %0, {%1,%2};" : "=l"(yp[j]) : "f"(y0), "f"(y1));
        asm("mov.b64 %0, {%1,%2};" : "=l"(zp[j]) : "f"(z0), "f"(z1));
        dist[2 * j] = 1e10f;
        dist[2 * j + 1] = 1e10f;
    }

    float qx = X[0], qy = X[1], qz = X[2];
    if (t == 0) { O[0] = qx; O[1] = qy; O[2] = qz; }
    __syncthreads();

    for (int it = 1; it < Sc; ++it) {
        float nqx = -qx, nqy = -qy, nqz = -qz;
        unsigned long long nq_x, nq_y, nq_z;
        asm("mov.b64 %0, {%1,%1};" : "=l"(nq_x) : "f"(nqx));
        asm("mov.b64 %0, {%1,%1};" : "=l"(nq_y) : "f"(nqy));
        asm("mov.b64 %0, {%1,%1};" : "=l"(nq_z) : "f"(nqz));

        unsigned best = 0u;   // dist bits (all dists >= 0)
        int bi = 0x7fffffff;
#pragma unroll
        for (int j = 0; j < 8; j++) {
            unsigned long long dx, dy, dz, sx, sy, sz, s;
            asm("add.rn.f32x2 %0, %1, %2;" : "=l"(dx) : "l"(xp[j]), "l"(nq_x));
            asm("add.rn.f32x2 %0, %1, %2;" : "=l"(dy) : "l"(yp[j]), "l"(nq_y));
            asm("add.rn.f32x2 %0, %1, %2;" : "=l"(dz) : "l"(zp[j]), "l"(nq_z));
            asm("mul.rn.f32x2 %0, %1, %1;" : "=l"(sx) : "l"(dx));
            asm("mul.rn.f32x2 %0, %1, %1;" : "=l"(sy) : "l"(dy));
            asm("mul.rn.f32x2 %0, %1, %1;" : "=l"(sz) : "l"(dz));
            asm("add.rn.f32x2 %0, %1, %2;" : "=l"(s) : "l"(sx), "l"(sy));
            asm("add.rn.f32x2 %0, %1, %2;" : "=l"(s) : "l"(s), "l"(sz));
            float d0, d1;
            asm("mov.b64 {%0,%1}, %2;" : "=f"(d0), "=f"(d1) : "l"(s));
            float nd0 = fminf(dist[2 * j], d0);
            dist[2 * j] = nd0;
            if (__float_as_uint(nd0) > best) { best = __float_as_uint(nd0); bi = 16 * t + 2 * j; }
            float nd1 = fminf(dist[2 * j + 1], d1);
            dist[2 * j + 1] = nd1;
            if (__float_as_uint(nd1) > best) { best = __float_as_uint(nd1); bi = 16 * t + 2 * j + 1; }
        }
        // warp argmax: one redux + ballot + one shfl (lowest lane = lowest index)
        unsigned wmax = __reduce_max_sync(FULLM, best);
        unsigned msk = __ballot_sync(FULLM, best == wmax);
        int src = __ffs(msk) - 1;
        int wbi = __shfl_sync(FULLM, bi, src);
        if ((t & 31) == 0) {
            unsigned long long key = ((unsigned long long)wmax << 32) |
                                     (unsigned long long)(0xffffffffu - (unsigned)wbi);
            atomicMax(&s_key[it & 3], key);
        }
        if (t == 0) s_key[(it + 2) & 3] = 0ull;  // slot reuse separated by 2 barriers
        __syncthreads();
        unsigned long long key = s_key[it & 3];
        int sel = (int)(0xffffffffu - (unsigned)(key & 0xffffffffu));
        qx = s_x[3 * sel + 0];
        qy = s_x[3 * sel + 1];
        qz = s_x[3 * sel + 2];
        if (t == 0) { O[3 * it + 0] = qx; O[3 * it + 1] = qy; O[3 * it + 2] = qz; }
    }
}

// ---------------- kernel 2: KNN (top-32 smallest) ----------------------------
__global__ __launch_bounds__(256) void knn_kernel(const float* __restrict__ newxyz) {
    extern __shared__ float4 s_pts[];
    int b = blockIdx.x >> 8;        // 256 groups per batch
    int grp = blockIdx.x & 255;
    const float4* P = g_xyzw + (size_t)b * Nc;
    for (int i = threadIdx.x; i < Nc; i += 256) s_pts[i] = P[i];
    __syncthreads();

    int warp = threadIdx.x >> 5, lane = threadIdx.x & 31;
    int s = grp * 8 + warp;
    int bs = b * Sc + s;
    float cx = newxyz[3 * bs], cy = newxyz[3 * bs + 1], cz = newxyz[3 * bs + 2];
    float cn = __fadd_rn(__fadd_rn(__fmul_rn(cx, cx), __fmul_rn(cy, cy)), __fmul_rn(cz, cz));

    float4 p = s_pts[lane];
    float dot = __fadd_rn(__fadd_rn(__fmul_rn(cx, p.x), __fmul_rn(cy, p.y)), __fmul_rn(cz, p.z));
    float kd = __fadd_rn(__fsub_rn(cn, __fmul_rn(2.0f, dot)), p.w);
    int ki = lane;

    float cm = kd;
#pragma unroll
    for (int o = 16; o; o >>= 1) cm = fmaxf(cm, __shfl_xor_sync(FULLM, cm, o));

    for (int base = 32; base < Nc; base += 32) {
        p = s_pts[base + lane];
        dot = __fadd_rn(__fadd_rn(__fmul_rn(cx, p.x), __fmul_rn(cy, p.y)), __fmul_rn(cz, p.z));
        float d = __fadd_rn(__fsub_rn(cn, __fmul_rn(2.0f, dot)), p.w);
        unsigned m = __ballot_sync(FULLM, d < cm);
        while (m) {
            int src = __ffs(m) - 1;
            m &= m - 1;
            float dn = __shfl_sync(FULLM, d, src);
            if (dn < cm) {
                unsigned mm = __ballot_sync(FULLM, kd == cm);
                int vic = __ffs(mm) - 1;
                if (lane == vic) { kd = dn; ki = base + src; }
                float v = kd;
#pragma unroll
                for (int o = 16; o; o >>= 1) v = fmaxf(v, __shfl_xor_sync(FULLM, v, o));
                cm = v;
            }
        }
    }
    g_knn[bs * 32 + lane] = ki;
}

// ---------------- kernels 3/5/7: 1x1 conv layers ------------------------------
template <int LAYER>
__global__ __launch_bounds__(256) void mlp_kernel(const float* __restrict__ W,
                                                  const float* __restrict__ Bias,
                                                  const float* __restrict__ pts,
                                                  const float* __restrict__ newxyz) {
    constexpr int CIN = (LAYER == 1) ? 35 : 64;
    constexpr int COUT = (LAYER == 3) ? 128 : 64;
    constexpr int TPR = COUT / 32;
    constexpr int RPB = 256 / TPR;

    const float* fin = (LAYER == 2) ? g_feat1 : g_feat2;
    float* fout = (LAYER == 1) ? g_feat1 : (LAYER == 2) ? g_feat2 : g_feat3;

    __shared__ float s_w[CIN * COUT];
    __shared__ float s_b[COUT];
    __shared__ float s_a[64], s_c[64];

    for (int idx = threadIdx.x; idx < CIN * COUT; idx += 256) {
        int o = idx / CIN, c = idx % CIN;
        s_w[c * COUT + o] = W[idx];
    }
    if (threadIdx.x < COUT) s_b[threadIdx.x] = Bias[threadIdx.x];
    if (LAYER > 1 && threadIdx.x < CIN) {
        s_a[threadIdx.x] = g_ab[threadIdx.x];
        s_c[threadIdx.x] = g_ab[CIN + threadIdx.x];
    }
    __syncthreads();

    int r = blockIdx.x * RPB + (threadIdx.x & (RPB - 1));
    int ot = (threadIdx.x / RPB) * 32;

    float in[CIN];
    if (LAYER == 1) {
        int b = r >> 16;
        int rem = r & 65535;
        int s = rem >> 5;
        int n = g_knn[r];
        float4 p = g_xyzw[b * Nc + n];
        int bs = b * Sc + s;
        in[0] = p.x - newxyz[3 * bs + 0];
        in[1] = p.y - newxyz[3 * bs + 1];
        in[2] = p.z - newxyz[3 * bs + 2];
        const float4* pp = (const float4*)(pts + (size_t)(b * Nc + n) * Dc);
#pragma unroll
        for (int q = 0; q < 8; q++) {
            float4 v = pp[q];
            in[3 + 4 * q] = v.x; in[4 + 4 * q] = v.y;
            in[5 + 4 * q] = v.z; in[6 + 4 * q] = v.w;
        }
    } else {
#pragma unroll
        for (int c = 0; c < CIN; c++) {
            float xv = fin[(size_t)c * Rc + r];
            in[c] = fmaxf(fmaf(s_a[c], xv, s_c[c]), 0.0f);
        }
    }

    float acc[32];
#pragma unroll
    for (int oo = 0; oo < 32; oo++) acc[oo] = s_b[ot + oo];
#pragma unroll
    for (int c = 0; c < CIN; c++) {
        float v = in[c];
        const float4* wr = (const float4*)(s_w + c * COUT + ot);
#pragma unroll
        for (int o4 = 0; o4 < 8; o4++) {
            float4 w = wr[o4];
            acc[4 * o4 + 0] = fmaf(v, w.x, acc[4 * o4 + 0]);
            acc[4 * o4 + 1] = fmaf(v, w.y, acc[4 * o4 + 1]);
            acc[4 * o4 + 2] = fmaf(v, w.z, acc[4 * o4 + 2]);
            acc[4 * o4 + 3] = fmaf(v, w.w, acc[4 * o4 + 3]);
        }
    }
#pragma unroll
    for (int oo = 0; oo < 32; oo++) fout[(size_t)(ot + oo) * Rc + r] = acc[oo];
}

// ---------------- BN statistics -----------------------------------------------
__global__ void zero_stats() { g_stats[threadIdx.x] = 0.0f; }

__global__ __launch_bounds__(256) void stats_kernel(int which) {
    const float* f = (which == 0) ? g_feat1 : (which == 1) ? g_feat2 : g_feat3;
    int o = blockIdx.x >> 5;
    int ch = blockIdx.x & 31;
    const float4* p = (const float4*)(f + (size_t)o * Rc) + (size_t)ch * (Rc / 32 / 4);
    float s = 0.0f, sq = 0.0f;
    for (int i = threadIdx.x; i < Rc / 32 / 4; i += 256) {
        float4 v = p[i];
        s += v.x + v.y + v.z + v.w;
        sq = fmaf(v.x, v.x, sq);
        sq = fmaf(v.y, v.y, sq);
        sq = fmaf(v.z, v.z, sq);
        sq = fmaf(v.w, v.w, sq);
    }
#pragma unroll
    for (int off = 16; off; off >>= 1) {
        s += __shfl_xor_sync(FULLM, s, off);
        sq += __shfl_xor_sync(FULLM, sq, off);
    }
    __shared__ float sh[16];
    int warp = threadIdx.x >> 5, lane = threadIdx.x & 31;
    if (lane == 0) { sh[warp] = s; sh[8 + warp] = sq; }
    __syncthreads();
    if (threadIdx.x == 0) {
        float ts = 0.0f, tq = 0.0f;
        for (int w = 0; w < 8; w++) { ts += sh[w]; tq += sh[8 + w]; }
        atomicAdd(&g_stats[o], ts);
        atomicAdd(&g_stats[128 + o], tq);
    }
}

__global__ void finalize_kernel(const float* __restrict__ g,
                                const float* __restrict__ be, int C) {
    int o = threadIdx.x;
    if (o < C) {
        const float inv = 1.0f / (float)Rc;
        float mu = g_stats[o] * inv;
        float var = g_stats[128 + o] * inv - mu * mu;
        float a = g[o] * rsqrtf(var + 1e-5f);
        g_ab[o] = a;
        g_ab[C + o] = fmaf(-mu, a, be[o]);
    }
}

// ---------------- kernel 8: BN+ReLU+maxpool over K ----------------------------
__global__ __launch_bounds__(256) void maxpool_kernel(float* __restrict__ outp) {
    int idx = blockIdx.x * 256 + threadIdx.x;  // (b*S+s)*128 + o
    int o = idx & 127;
    int bs = idx >> 7;
    float a = g_ab[o], c = g_ab[128 + o];
    const float4* p = (const float4*)(g_feat3 + (size_t)o * Rc + (size_t)bs * 32);
    float m = 0.0f;  // relu baked in
#pragma unroll
    for (int q = 0; q < 8; q++) {
        float4 v = p[q];
        m = fmaxf(m, fmaf(a, v.x, c));
        m = fmaxf(m, fmaf(a, v.y, c));
        m = fmaxf(m, fmaf(a, v.z, c));
        m = fmaxf(m, fmaf(a, v.w, c));
    }
    outp[idx] = m;
}

// ---------------- launch --------------------------------------------------------
extern "C" void kernel_launch(void* const* d_in, const int* in_sizes, int n_in,
                              void* d_out, int out_size) {
    const float* xyz = (const float*)d_in[0];
    const float* points = (const float*)d_in[1];
    const float* w1 = (const float*)d_in[2];
    const float* b1 = (const float*)d_in[3];
    const float* g1 = (const float*)d_in[4];
    const float* be1 = (const float*)d_in[5];
    const float* w2 = (const float*)d_in[6];
    const float* b2 = (const float*)d_in[7];
    const float* g2 = (const float*)d_in[8];
    const float* be2 = (const float*)d_in[9];
    const float* w3 = (const float*)d_in[10];
    const float* b3 = (const float*)d_in[11];
    const float* g3 = (const float*)d_in[12];
    const float* be3 = (const float*)d_in[13];

    float* out = (float*)d_out;
    float* out_xyz = out;                        // [B,S,3]
    float* out_pts = out + (size_t)Bc * Sc * 3;  // [B,S,128]

    prep_kernel<<<(Bc * Nc + 255) / 256, 256>>>(xyz);

    cudaFuncSetAttribute(fps_kernel, cudaFuncAttributeMaxDynamicSharedMemorySize, 0);
    fps_kernel<<<Bc, 512>>>(xyz, out_xyz);

    cudaFuncSetAttribute(knn_kernel, cudaFuncAttributeMaxDynamicSharedMemorySize,
                         Nc * (int)sizeof(float4));
    knn_kernel<<<Bc * (Sc / 8), 256, Nc * sizeof(float4)>>>(out_xyz);

    mlp_kernel<1><<<Rc / 128, 256>>>(w1, b1, points, out_xyz);
    zero_stats<<<1, 256>>>();
    stats_kernel<<<64 * 32, 256>>>(0);
    finalize_kernel<<<1, 128>>>(g1, be1, 64);

    mlp_kernel<2><<<Rc / 128, 256>>>(w2, b2, points, out_xyz);
    zero_stats<<<1, 256>>>();
    stats_kernel<<<64 * 32, 256>>>(1);
    finalize_kernel<<<1, 128>>>(g2, be2, 64);

    mlp_kernel<3><<<Rc / 64, 256>>>(w3, b3, points, out_xyz);
    zero_stats<<<1, 256>>>();
    stats_kernel<<<128 * 32, 256>>>(2);
    finalize_kernel<<<1, 128>>>(g3, be3, 128);

    maxpool_kernel<<<(Bc * Sc * 128) / 256, 256>>>(out_pts);
}

// round 5
// speedup vs baseline: 1.3454x; 1.0872x over previous
#include <cuda_runtime.h>

#define FULLM 0xffffffffu

static constexpr int Bc = 8, Nc = 8192, Dc = 32, Sc = 2048, Kc = 32;
static constexpr int Rc = Bc * Sc * Kc;  // 524288 rows

// ---------------- scratch ----------------------------------------------------
__device__ float4 g_xyzw[Bc * Nc];
__device__ int    g_knn[Rc];
__device__ float  g_feat1[(long long)Rc * 64];
__device__ float  g_feat2[(long long)Rc * 64];
__device__ float  g_feat3[(long long)Rc * 128];
__device__ float  g_stats[256];
__device__ float  g_ab[256];

__device__ __forceinline__ unsigned long long pk2(float lo, float hi) {
    unsigned long long r;
    asm("mov.b64 %0, {%1,%2};" : "=l"(r) : "f"(lo), "f"(hi));
    return r;
}
__device__ __forceinline__ void upk2(unsigned long long v, float& lo, float& hi) {
    asm("mov.b64 {%0,%1}, %2;" : "=f"(lo), "=f"(hi) : "l"(v));
}
#define FMA2(acc, a, b) \
    asm("fma.rn.f32x2 %0, %1, %2, %3;" : "=l"(acc) : "l"(a), "l"(b), "l"(acc))

// ---------------- kernel 0: pack xyz + squared norm ---------------------------
__global__ void prep_kernel(const float* __restrict__ xyz) {
    int i = blockIdx.x * blockDim.x + threadIdx.x;
    if (i < Bc * Nc) {
        float x = xyz[3 * i + 0], y = xyz[3 * i + 1], z = xyz[3 * i + 2];
        float w = __fadd_rn(__fadd_rn(__fmul_rn(x, x), __fmul_rn(y, y)), __fmul_rn(z, z));
        g_xyzw[i] = make_float4(x, y, z, w);
    }
}

// ---------------- kernel 1: farthest point sampling ---------------------------
// 512 threads x 16 points, packed f32x2 (bit-exact per-lane IEEE RN).
// No atomics: per-warp (val,idx) -> STS into double-buffered slots -> one
// barrier -> every warp redux-reduces the 16 slots. Warp w owns contiguous
// ascending indices, so lowest tied warp == smallest index (JAX tie-break).
__global__ __launch_bounds__(512) void fps_kernel(const float* __restrict__ xyz,
                                                  float* __restrict__ out_xyz) {
    const int b = blockIdx.x;
    const float* X = xyz + (size_t)b * Nc * 3;
    float* O = out_xyz + (size_t)b * Sc * 3;
    const int t = threadIdx.x;
    const int lane = t & 31, w = t >> 5;

    __shared__ float s_x[Nc * 3];                 // 96KB point stash
    __shared__ unsigned s_wval[2][16];
    __shared__ unsigned s_widx[2][16];

    for (int i = t; i < Nc * 3; i += 512) s_x[i] = X[i];

    unsigned long long xp[8], yp[8], zp[8];
    float dist[16];
#pragma unroll
    for (int j = 0; j < 8; j++) {
        int i0 = 16 * t + 2 * j;
        xp[j] = pk2(X[3 * i0 + 0], X[3 * i0 + 3]);
        yp[j] = pk2(X[3 * i0 + 1], X[3 * i0 + 4]);
        zp[j] = pk2(X[3 * i0 + 2], X[3 * i0 + 5]);
        dist[2 * j] = 1e10f;
        dist[2 * j + 1] = 1e10f;
    }

    float qx = X[0], qy = X[1], qz = X[2];
    if (t == 0) { O[0] = qx; O[1] = qy; O[2] = qz; }
    __syncthreads();

    for (int it = 1; it < Sc; ++it) {
        unsigned long long nq_x = pk2(-qx, -qx), nq_y = pk2(-qy, -qy), nq_z = pk2(-qz, -qz);

        float bestf = 0.0f;
#pragma unroll
        for (int j = 0; j < 8; j++) {
            unsigned long long dx, dy, dz, sx, sy, sz, s;
            asm("add.rn.f32x2 %0, %1, %2;" : "=l"(dx) : "l"(xp[j]), "l"(nq_x));
            asm("add.rn.f32x2 %0, %1, %2;" : "=l"(dy) : "l"(yp[j]), "l"(nq_y));
            asm("add.rn.f32x2 %0, %1, %2;" : "=l"(dz) : "l"(zp[j]), "l"(nq_z));
            asm("mul.rn.f32x2 %0, %1, %1;" : "=l"(sx) : "l"(dx));
            asm("mul.rn.f32x2 %0, %1, %1;" : "=l"(sy) : "l"(dy));
            asm("mul.rn.f32x2 %0, %1, %1;" : "=l"(sz) : "l"(dz));
            asm("add.rn.f32x2 %0, %1, %2;" : "=l"(s) : "l"(sx), "l"(sy));
            asm("add.rn.f32x2 %0, %1, %2;" : "=l"(s) : "l"(s), "l"(sz));
            float d0, d1;
            upk2(s, d0, d1);
            float nd0 = fminf(dist[2 * j], d0);
            dist[2 * j] = nd0;
            bestf = fmaxf(bestf, nd0);
            float nd1 = fminf(dist[2 * j + 1], d1);
            dist[2 * j + 1] = nd1;
            bestf = fmaxf(bestf, nd1);
        }
        // warp argmax: value redux, then rescan matching lanes for the index
        unsigned bb = __float_as_uint(bestf);              // dists >= 0
        unsigned wmax = __reduce_max_sync(FULLM, bb);
        unsigned cand = 0xffffffffu;
        if (bb == wmax) {
#pragma unroll
            for (int k = 15; k >= 0; k--)
                if (__float_as_uint(dist[k]) == wmax) cand = (unsigned)(16 * t + k);
        }
        unsigned widx = __reduce_min_sync(FULLM, cand);
        int p = it & 1;
        if (lane == 0) { s_wval[p][w] = wmax; s_widx[p][w] = widx; }
        __syncthreads();
        // block argmax: all warps reduce the 16 per-warp slots
        unsigned v = (lane < 16) ? s_wval[p][lane] : 0u;
        unsigned m2 = __reduce_max_sync(FULLM, v);
        unsigned msk = __ballot_sync(FULLM, (lane < 16) && (v == m2));
        int srcw = __ffs(msk) - 1;                          // lowest warp = smallest idx
        int sel = (int)s_widx[p][srcw];
        qx = s_x[3 * sel + 0];
        qy = s_x[3 * sel + 1];
        qz = s_x[3 * sel + 2];
        if (t == 0) { O[3 * it + 0] = qx; O[3 * it + 1] = qy; O[3 * it + 2] = qz; }
    }
}

// ---------------- kernel 2: KNN (top-32 smallest) ----------------------------
__global__ __launch_bounds__(256) void knn_kernel(const float* __restrict__ newxyz) {
    extern __shared__ float4 s_pts[];
    int b = blockIdx.x >> 8;
    int grp = blockIdx.x & 255;
    const float4* P = g_xyzw + (size_t)b * Nc;
    for (int i = threadIdx.x; i < Nc; i += 256) s_pts[i] = P[i];
    __syncthreads();

    int warp = threadIdx.x >> 5, lane = threadIdx.x & 31;
    int s = grp * 8 + warp;
    int bs = b * Sc + s;
    float cx = newxyz[3 * bs], cy = newxyz[3 * bs + 1], cz = newxyz[3 * bs + 2];
    float cn = __fadd_rn(__fadd_rn(__fmul_rn(cx, cx), __fmul_rn(cy, cy)), __fmul_rn(cz, cz));

    float4 p = s_pts[lane];
    float dot = __fadd_rn(__fadd_rn(__fmul_rn(cx, p.x), __fmul_rn(cy, p.y)), __fmul_rn(cz, p.z));
    float kd = __fadd_rn(__fsub_rn(cn, __fmul_rn(2.0f, dot)), p.w);
    int ki = lane;

    float cm = kd;
#pragma unroll
    for (int o = 16; o; o >>= 1) cm = fmaxf(cm, __shfl_xor_sync(FULLM, cm, o));

    for (int base = 32; base < Nc; base += 32) {
        p = s_pts[base + lane];
        dot = __fadd_rn(__fadd_rn(__fmul_rn(cx, p.x), __fmul_rn(cy, p.y)), __fmul_rn(cz, p.z));
        float d = __fadd_rn(__fsub_rn(cn, __fmul_rn(2.0f, dot)), p.w);
        unsigned m = __ballot_sync(FULLM, d < cm);
        while (m) {
            int src = __ffs(m) - 1;
            m &= m - 1;
            float dn = __shfl_sync(FULLM, d, src);
            if (dn < cm) {
                unsigned mm = __ballot_sync(FULLM, kd == cm);
                int vic = __ffs(mm) - 1;
                if (lane == vic) { kd = dn; ki = base + src; }
                float v = kd;
#pragma unroll
                for (int o = 16; o; o >>= 1) v = fmaxf(v, __shfl_xor_sync(FULLM, v, o));
                cm = v;
            }
        }
    }
    g_knn[bs * 32 + lane] = ki;
}

// ---------------- kernel 3: layer-1 conv (gather) -----------------------------
__global__ __launch_bounds__(256) void mlp1_kernel(const float* __restrict__ W,
                                                   const float* __restrict__ Bias,
                                                   const float* __restrict__ pts,
                                                   const float* __restrict__ newxyz) {
    constexpr int CIN = 35, COUT = 64;
    __shared__ float s_w[CIN * COUT];
    __shared__ float s_b[COUT];
    for (int idx = threadIdx.x; idx < CIN * COUT; idx += 256) {
        int o = idx / CIN, c = idx % CIN;
        s_w[c * COUT + o] = W[idx];
    }
    if (threadIdx.x < COUT) s_b[threadIdx.x] = Bias[threadIdx.x];
    __syncthreads();

    int r = blockIdx.x * 128 + (threadIdx.x & 127);
    int ot = (threadIdx.x / 128) * 32;

    float in[CIN];
    {
        int b = r >> 16;
        int rem = r & 65535;
        int s = rem >> 5;
        int n = g_knn[r];
        float4 p = g_xyzw[b * Nc + n];
        int bs = b * Sc + s;
        in[0] = p.x - newxyz[3 * bs + 0];
        in[1] = p.y - newxyz[3 * bs + 1];
        in[2] = p.z - newxyz[3 * bs + 2];
        const float4* pp = (const float4*)(pts + (size_t)(b * Nc + n) * Dc);
#pragma unroll
        for (int q = 0; q < 8; q++) {
            float4 v = pp[q];
            in[3 + 4 * q] = v.x; in[4 + 4 * q] = v.y;
            in[5 + 4 * q] = v.z; in[6 + 4 * q] = v.w;
        }
    }

    float acc[32];
#pragma unroll
    for (int oo = 0; oo < 32; oo++) acc[oo] = s_b[ot + oo];
#pragma unroll
    for (int c = 0; c < CIN; c++) {
        float v = in[c];
        const float4* wr = (const float4*)(s_w + c * COUT + ot);
#pragma unroll
        for (int o4 = 0; o4 < 8; o4++) {
            float4 wv = wr[o4];
            acc[4 * o4 + 0] = fmaf(v, wv.x, acc[4 * o4 + 0]);
            acc[4 * o4 + 1] = fmaf(v, wv.y, acc[4 * o4 + 1]);
            acc[4 * o4 + 2] = fmaf(v, wv.z, acc[4 * o4 + 2]);
            acc[4 * o4 + 3] = fmaf(v, wv.w, acc[4 * o4 + 3]);
        }
    }
#pragma unroll
    for (int oo = 0; oo < 32; oo++) g_feat1[(size_t)(ot + oo) * Rc + r] = acc[oo];
}

// ---------------- layers 2/3: register-tiled, f32x2, fused BN-stats -----------
// Thread: 4 rows x 16 outs (8 f32x2 channel-pairs). Weights read once per
// 4 rows (4x fewer LDS). fma.rn.f32x2 = bitwise-identical per-lane IEEE RN.
// Epilogue accumulates per-channel sum/sumsq into g_stats (stats pass fused).
// fin/fout are selected INSIDE the kernel (device symbols are not addressable
// from host code — that was the Round-4 bug).
template <int LAYER>
__global__ __launch_bounds__(256) void mlp23_kernel(const float* __restrict__ W,
                                                    const float* __restrict__ Bias) {
    constexpr int CIN = 64;
    constexpr int COUT = (LAYER == 3) ? 128 : 64;
    constexpr int TG = COUT / 16;   // warps per row-group
    constexpr int RPB = (8 / TG) * 128;

    const float* fin = (LAYER == 2) ? g_feat1 : g_feat2;
    float* fout = (LAYER == 2) ? g_feat2 : g_feat3;

    __shared__ __align__(16) float s_w[CIN * COUT];
    __shared__ float s_b[COUT];
    __shared__ float s_a[CIN], s_cc[CIN];

    for (int idx = threadIdx.x; idx < CIN * COUT; idx += 256) {
        int o = idx / CIN, c = idx % CIN;
        s_w[c * COUT + o] = W[idx];
    }
    if (threadIdx.x < COUT) s_b[threadIdx.x] = Bias[threadIdx.x];
    if (threadIdx.x < CIN) {
        s_a[threadIdx.x] = g_ab[threadIdx.x];
        s_cc[threadIdx.x] = g_ab[CIN + threadIdx.x];
    }
    __syncthreads();

    int w = threadIdx.x >> 5, lane = threadIdx.x & 31;
    int tile = w % TG, rg = w / TG;
    int row0 = blockIdx.x * RPB + rg * 128 + lane;
    int ot = tile * 16;

    unsigned long long acc2[4][8];
#pragma unroll
    for (int o = 0; o < 8; o++) {
        unsigned long long bv = pk2(s_b[ot + 2 * o], s_b[ot + 2 * o + 1]);
#pragma unroll
        for (int k = 0; k < 4; k++) acc2[k][o] = bv;
    }

#pragma unroll 4
    for (int c = 0; c < CIN; c++) {
        float a = s_a[c], cc = s_cc[c];
        const float* col = fin + (size_t)c * Rc + row0;
        unsigned long long ind[4];
#pragma unroll
        for (int k = 0; k < 4; k++) {
            float iv = fmaxf(fmaf(a, col[32 * k], cc), 0.0f);
            ind[k] = pk2(iv, iv);
        }
        const ulonglong2* wp = (const ulonglong2*)(s_w + c * COUT + ot);
#pragma unroll
        for (int o4 = 0; o4 < 4; o4++) {
            ulonglong2 wv = wp[o4];
#pragma unroll
            for (int k = 0; k < 4; k++) {
                FMA2(acc2[k][2 * o4 + 0], ind[k], wv.x);
                FMA2(acc2[k][2 * o4 + 1], ind[k], wv.y);
            }
        }
    }

    // store + fused stats
#pragma unroll
    for (int o = 0; o < 8; o++) {
        float lo[4], hi[4];
#pragma unroll
        for (int k = 0; k < 4; k++) {
            upk2(acc2[k][o], lo[k], hi[k]);
            fout[(size_t)(ot + 2 * o) * Rc + row0 + 32 * k] = lo[k];
            fout[(size_t)(ot + 2 * o + 1) * Rc + row0 + 32 * k] = hi[k];
        }
        float su0 = (lo[0] + lo[1]) + (lo[2] + lo[3]);
        float su1 = (hi[0] + hi[1]) + (hi[2] + hi[3]);
        float sq0 = 0.0f, sq1 = 0.0f;
#pragma unroll
        for (int k = 0; k < 4; k++) {
            sq0 = fmaf(lo[k], lo[k], sq0);
            sq1 = fmaf(hi[k], hi[k], sq1);
        }
#pragma unroll
        for (int off = 16; off; off >>= 1) {
            su0 += __shfl_xor_sync(FULLM, su0, off);
            su1 += __shfl_xor_sync(FULLM, su1, off);
            sq0 += __shfl_xor_sync(FULLM, sq0, off);
            sq1 += __shfl_xor_sync(FULLM, sq1, off);
        }
        if (lane == 0) {
            atomicAdd(&g_stats[ot + 2 * o], su0);
            atomicAdd(&g_stats[ot + 2 * o + 1], su1);
            atomicAdd(&g_stats[128 + ot + 2 * o], sq0);
            atomicAdd(&g_stats[128 + ot + 2 * o + 1], sq1);
        }
    }
}

// ---------------- BN statistics (layer 1 only) --------------------------------
__global__ void zero_stats() { g_stats[threadIdx.x] = 0.0f; }

__global__ __launch_bounds__(256) void stats_kernel() {
    const float* f = g_feat1;
    int o = blockIdx.x >> 5;
    int ch = blockIdx.x & 31;
    const float4* p = (const float4*)(f + (size_t)o * Rc) + (size_t)ch * (Rc / 32 / 4);
    float s = 0.0f, sq = 0.0f;
    for (int i = threadIdx.x; i < Rc / 32 / 4; i += 256) {
        float4 v = p[i];
        s += v.x + v.y + v.z + v.w;
        sq = fmaf(v.x, v.x, sq);
        sq = fmaf(v.y, v.y, sq);
        sq = fmaf(v.z, v.z, sq);
        sq = fmaf(v.w, v.w, sq);
    }
#pragma unroll
    for (int off = 16; off; off >>= 1) {
        s += __shfl_xor_sync(FULLM, s, off);
        sq += __shfl_xor_sync(FULLM, sq, off);
    }
    __shared__ float sh[16];
    int warp = threadIdx.x >> 5, lane = threadIdx.x & 31;
    if (lane == 0) { sh[warp] = s; sh[8 + warp] = sq; }
    __syncthreads();
    if (threadIdx.x == 0) {
        float ts = 0.0f, tq = 0.0f;
        for (int ww = 0; ww < 8; ww++) { ts += sh[ww]; tq += sh[8 + ww]; }
        atomicAdd(&g_stats[o], ts);
        atomicAdd(&g_stats[128 + o], tq);
    }
}

__global__ void finalize_kernel(const float* __restrict__ g,
                                const float* __restrict__ be, int C) {
    int o = threadIdx.x;
    if (o < C) {
        const float inv = 1.0f / (float)Rc;
        float mu = g_stats[o] * inv;
        float var = g_stats[128 + o] * inv - mu * mu;
        float a = g[o] * rsqrtf(var + 1e-5f);
        g_ab[o] = a;
        g_ab[C + o] = fmaf(-mu, a, be[o]);
    }
}

// ---------------- BN+ReLU+maxpool over K --------------------------------------
__global__ __launch_bounds__(256) void maxpool_kernel(float* __restrict__ outp) {
    int idx = blockIdx.x * 256 + threadIdx.x;
    int o = idx & 127;
    int bs = idx >> 7;
    float a = g_ab[o], c = g_ab[128 + o];
    const float4* p = (const float4*)(g_feat3 + (size_t)o * Rc + (size_t)bs * 32);
    float m = 0.0f;
#pragma unroll
    for (int q = 0; q < 8; q++) {
        float4 v = p[q];
        m = fmaxf(m, fmaf(a, v.x, c));
        m = fmaxf(m, fmaf(a, v.y, c));
        m = fmaxf(m, fmaf(a, v.z, c));
        m = fmaxf(m, fmaf(a, v.w, c));
    }
    outp[idx] = m;
}

// ---------------- launch --------------------------------------------------------
extern "C" void kernel_launch(void* const* d_in, const int* in_sizes, int n_in,
                              void* d_out, int out_size) {
    const float* xyz = (const float*)d_in[0];
    const float* points = (const float*)d_in[1];
    const float* w1 = (const float*)d_in[2];
    const float* b1 = (const float*)d_in[3];
    const float* g1 = (const float*)d_in[4];
    const float* be1 = (const float*)d_in[5];
    const float* w2 = (const float*)d_in[6];
    const float* b2 = (const float*)d_in[7];
    const float* g2 = (const float*)d_in[8];
    const float* be2 = (const float*)d_in[9];
    const float* w3 = (const float*)d_in[10];
    const float* b3 = (const float*)d_in[11];
    const float* g3 = (const float*)d_in[12];
    const float* be3 = (const float*)d_in[13];

    float* out = (float*)d_out;
    float* out_xyz = out;
    float* out_pts = out + (size_t)Bc * Sc * 3;

    prep_kernel<<<(Bc * Nc + 255) / 256, 256>>>(xyz);
    fps_kernel<<<Bc, 512>>>(xyz, out_xyz);

    cudaFuncSetAttribute(knn_kernel, cudaFuncAttributeMaxDynamicSharedMemorySize,
                         Nc * (int)sizeof(float4));
    knn_kernel<<<Bc * (Sc / 8), 256, Nc * sizeof(float4)>>>(out_xyz);

    // layer 1 (separate stats pass)
    mlp1_kernel<<<Rc / 128, 256>>>(w1, b1, points, out_xyz);
    zero_stats<<<1, 256>>>();
    stats_kernel<<<64 * 32, 256>>>();
    finalize_kernel<<<1, 128>>>(g1, be1, 64);

    // layer 2 (stats fused)
    zero_stats<<<1, 256>>>();
    mlp23_kernel<2><<<Rc / 256, 256>>>(w2, b2);
    finalize_kernel<<<1, 128>>>(g2, be2, 64);

    // layer 3 (stats fused)
    zero_stats<<<1, 256>>>();
    mlp23_kernel<3><<<Rc / 128, 256>>>(w3, b3);
    finalize_kernel<<<1, 128>>>(g3, be3, 128);

    maxpool_kernel<<<(Bc * Sc * 128) / 256, 256>>>(out_pts);
}